// round 12
// baseline (speedup 1.0000x reference)
#include <cuda_runtime.h>
#include <cuda_bf16.h>
#include <cuda_fp16.h>
#include <math.h>
#include <stdint.h>

// ---------------------------------------------------------------------------
// MS_MSA — round 12: k-chunk 64 (half the sync/issue tax) in vproj/final/xtx
// GEMMs; everything else from round 11 (908 us).
// ---------------------------------------------------------------------------

#define NTOK 65536
#define CCH  512
#define HH   256
#define WW   256

// ------------------------- scratch (device globals) ------------------------
__device__ __half g_vh[33554432];
__device__ __half g_xh[33554432];
__device__ __half g_xhT[33554432];
__device__ __half g_vmh[33554432];
__device__ __half g_pebh[33554432];
__device__ __half g_Fh[5242880];
__device__ __half g_W1h[40960];
__device__ __half g_W2h[40960];
__device__ __half g_WvTh[262144];
__device__ __half g_wpeTh[262144];
__device__ float  g_a[131072];
__device__ float  g_ss[131072];
__device__ float  g_bnp[4];
__device__ float  g_gpart[8388608];   // [32][512*512]
__device__ float  g_S[262144];
__device__ float  g_U[262144];
__device__ float  g_T2[262144];
__device__ float  g_gram[32768];
__device__ float  g_norms[1024];
__device__ float  g_attn[32768];

__device__ __constant__ int c_inner[25] = {
    -1,-1,-1,-1,-1, -1,0,1,2,-1, -1,3,4,5,-1, -1,6,7,8,-1, -1,-1,-1,-1,-1};
__device__ __constant__ int c_outer[25] = {
    0,1,2,3,4, 5,-1,-1,-1,6, 7,-1,-1,-1,8, 9,-1,-1,-1,10, 11,12,13,14,15};

// ------------------------------ SAR path -----------------------------------

__global__ void conv3_kernel(const float* __restrict__ sar,
                             const float* __restrict__ w,
                             const float* __restrict__ b,
                             float* __restrict__ a) {
    int n = blockIdx.x * 256 + threadIdx.x;
    if (n >= NTOK) return;
    int y = n >> 8, x = n & 255;
    #pragma unroll
    for (int co = 0; co < 2; co++) {
        float acc = b[co];
        #pragma unroll
        for (int ci = 0; ci < 2; ci++) {
            #pragma unroll
            for (int ky = 0; ky < 3; ky++) {
                int yy = y + ky - 1;
                if (yy < 0 || yy >= HH) continue;
                #pragma unroll
                for (int kx = 0; kx < 3; kx++) {
                    int xx = x + kx - 1;
                    if (xx < 0 || xx >= WW) continue;
                    acc += w[((co * 2 + ci) * 3 + ky) * 3 + kx] *
                           sar[ci * NTOK + (yy << 8) + xx];
                }
            }
        }
        a[co * NTOK + n] = acc;
    }
}

__global__ void bnstats_kernel(const float* __restrict__ a,
                               const float* __restrict__ gg,
                               const float* __restrict__ bb,
                               float* __restrict__ bnp) {
    int c = blockIdx.x;
    __shared__ float sh[512], sh2[512];
    float s = 0.f, s2 = 0.f;
    for (int i = threadIdx.x; i < NTOK; i += 512) {
        float v = a[c * NTOK + i];
        s += v; s2 += v * v;
    }
    sh[threadIdx.x] = s; sh2[threadIdx.x] = s2;
    __syncthreads();
    for (int st = 256; st > 0; st >>= 1) {
        if (threadIdx.x < st) {
            sh[threadIdx.x] += sh[threadIdx.x + st];
            sh2[threadIdx.x] += sh2[threadIdx.x + st];
        }
        __syncthreads();
    }
    if (threadIdx.x == 0) {
        float mean = sh[0] * (1.f / NTOK);
        float var = sh2[0] * (1.f / NTOK) - mean * mean;
        float sc = gg[c] * rsqrtf(var + 1e-5f);
        bnp[c * 2] = sc;
        bnp[c * 2 + 1] = bb[c] - mean * sc;
    }
}

__global__ void sobel_ss_kernel(const float* __restrict__ a,
                                const float* __restrict__ bnp,
                                const float* __restrict__ sb,
                                float* __restrict__ ss) {
    int n = blockIdx.x * 256 + threadIdx.x;
    if (n >= NTOK) return;
    int y = n >> 8, x = n & 255;
    float sc0 = bnp[0], sh0 = bnp[1], sc1 = bnp[2], sh1 = bnp[3];
    float t[3][3];
    #pragma unroll
    for (int ky = 0; ky < 3; ky++) {
        int yy = y + ky - 1;
        #pragma unroll
        for (int kx = 0; kx < 3; kx++) {
            int xx = x + kx - 1;
            if (yy >= 0 && yy < HH && xx >= 0 && xx < WW) {
                int idx = (yy << 8) + xx;
                t[ky][kx] = a[idx] * sc0 + sh0 + a[NTOK + idx] * sc1 + sh1;
            } else t[ky][kx] = 0.f;
        }
    }
    float gy = -(t[0][0] + 2.f * t[0][1] + t[0][2]) + (t[2][0] + 2.f * t[2][1] + t[2][2]);
    float gx = -(t[0][0] + 2.f * t[1][0] + t[2][0]) + (t[0][2] + 2.f * t[1][2] + t[2][2]);
    float s0 = gy + sb[0], s1 = gx + sb[1], s2 = gy + sb[2], s3 = gx + sb[3];
    float bc0 = a[n] * sc0 + sh0;
    float bc1 = a[NTOK + n] * sc1 + sh1;
    ss[n]        = sqrtf(s0 * s0 + s1 * s1) + bc0;
    ss[NTOK + n] = sqrtf(s2 * s2 + s3 * s3) + bc1;
}

__global__ void __launch_bounds__(256) fbuild_kernel(
    const float* __restrict__ ss, __half* __restrict__ F) {
    __shared__ float Fs[64 * 80];
    int p0 = blockIdx.x * 64;
    int tid = threadIdx.x;
    int pix = tid >> 2;
    int t4 = tid & 3;
    int n = p0 + pix;
    int y = n >> 8, x = n & 255;
    for (int t = t4; t < 25; t += 4) {
        int dy = t / 5, dx = t % 5;
        int yy = y + dy - 2, xx = x + dx - 2;
        bool ok = (yy >= 0 && yy < HH && xx >= 0 && xx < WW);
        float s0 = 0.f, s1 = 0.f;
        if (ok) {
            int idx = (yy << 8) + xx;
            s0 = ss[idx];
            s1 = ss[NTOK + idx];
        }
        int ii = c_inner[t];
        int s0slot, s1slot;
        if (ii >= 0) { s0slot = ii; s1slot = 9 + ii; }
        else { int oi = c_outer[t]; s0slot = 32 + oi; s1slot = 48 + oi; }
        Fs[pix * 80 + s0slot] = s0;
        Fs[pix * 80 + s1slot] = s1;
        int vslot = (t < 13) ? (19 + t) : (64 + t - 13);
        Fs[pix * 80 + vslot] = ok ? 1.f : 0.f;
    }
    if (t4 == 0) {
        Fs[pix * 80 + 18] = 1.f;
        Fs[pix * 80 + 76] = 0.f;
        Fs[pix * 80 + 77] = 0.f;
        Fs[pix * 80 + 78] = 0.f;
        Fs[pix * 80 + 79] = 0.f;
    }
    __syncthreads();
    __half* dst = F + (size_t)p0 * 80;
    for (int e = tid; e < 64 * 80; e += 256) dst[e] = __float2half(Fs[e]);
}

__global__ void wbuild_kernel(const float* __restrict__ w2c, const float* __restrict__ b2,
                              const float* __restrict__ w32, const float* __restrict__ b32,
                              const float* __restrict__ dw, const float* __restrict__ db,
                              __half* __restrict__ W1, __half* __restrict__ W2) {
    int c = threadIdx.x;
    float w20 = w2c[c * 2], w21 = w2c[c * 2 + 1], bb2 = b2[c], bbd = db[c];
    __half* o1 = W1 + c * 80;
    __half* o2 = W2 + c * 80;
    for (int k = 0; k < 80; k++) { o1[k] = __float2half(0.f); o2[k] = __float2half(0.f); }
    for (int t = 0; t < 25; t++) {
        float d = dw[c * 25 + t];
        bool ctr = (t == 12);
        int ii = c_inner[t];
        int s0slot, s1slot;
        if (ii >= 0) { s0slot = ii; s1slot = 9 + ii; }
        else { int oi = c_outer[t]; s0slot = 32 + oi; s1slot = 48 + oi; }
        o1[s0slot] = __float2half(d * w20 + (ctr ? w20 : 0.f));
        o1[s1slot] = __float2half(d * w21 + (ctr ? w21 : 0.f));
        int vslot = (t < 13) ? (19 + t) : (64 + t - 13);
        o1[vslot] = __float2half(d * bb2 + (ctr ? bb2 : 0.f));
        if (ii >= 0) {
            o2[s0slot] = __float2half(w32[c * 18 + ii]);
            o2[s1slot] = __float2half(w32[c * 18 + 9 + ii]);
        }
    }
    o1[18] = __float2half(bbd);
    o2[18] = __float2half(b32[c]);
}

// -------------------------- MMA / async helpers ------------------------------
__device__ __forceinline__ float f2tf32(float x) {
    float r;
    asm("cvt.rna.tf32.f32 %0, %1;" : "=f"(r) : "f"(x));
    return r;
}

__device__ __forceinline__ uint32_t ld_tf32(const float* p) {
    return __float_as_uint(f2tf32(*p));
}

__device__ __forceinline__ void mma_tf32(float* c, const uint32_t* a,
                                         const uint32_t* b) {
    asm volatile(
        "mma.sync.aligned.m16n8k8.row.col.f32.tf32.tf32.f32 "
        "{%0,%1,%2,%3}, {%4,%5,%6,%7}, {%8,%9}, {%0,%1,%2,%3};"
        : "+f"(c[0]), "+f"(c[1]), "+f"(c[2]), "+f"(c[3])
        : "r"(a[0]), "r"(a[1]), "r"(a[2]), "r"(a[3]), "r"(b[0]), "r"(b[1]));
}

__device__ __forceinline__ void mma_f16(float* c, const uint32_t* a,
                                        const uint32_t* b) {
    asm volatile(
        "mma.sync.aligned.m16n8k16.row.col.f32.f16.f16.f32 "
        "{%0,%1,%2,%3}, {%4,%5,%6,%7}, {%8,%9}, {%0,%1,%2,%3};"
        : "+f"(c[0]), "+f"(c[1]), "+f"(c[2]), "+f"(c[3])
        : "r"(a[0]), "r"(a[1]), "r"(a[2]), "r"(a[3]), "r"(b[0]), "r"(b[1]));
}

__device__ __forceinline__ void ldsm_x4(uint32_t addr, uint32_t& r0, uint32_t& r1,
                                        uint32_t& r2, uint32_t& r3) {
    asm volatile("ldmatrix.sync.aligned.m8n8.x4.shared.b16 {%0,%1,%2,%3}, [%4];"
                 : "=r"(r0), "=r"(r1), "=r"(r2), "=r"(r3) : "r"(addr));
}

__device__ __forceinline__ void ldsm_x2(uint32_t addr, uint32_t& r0, uint32_t& r1) {
    asm volatile("ldmatrix.sync.aligned.m8n8.x2.shared.b16 {%0,%1}, [%2];"
                 : "=r"(r0), "=r"(r1) : "r"(addr));
}

__device__ __forceinline__ uint32_t smaddr(const void* p) {
    return (uint32_t)__cvta_generic_to_shared(p);
}

__device__ __forceinline__ void cpasync16(uint32_t s, const void* g) {
    asm volatile("cp.async.cg.shared.global [%0], [%1], 16;" :: "r"(s), "l"(g));
}

__device__ __forceinline__ void cp_commit() {
    asm volatile("cp.async.commit_group;");
}

// -------------------- fp16 GEMM: C[M,512] = A[M,512] @ BT^T ------------------
// k-chunk 64: smem tile 128 rows x 72 halves (64 data + 8 pad) = 18432 B.
// MODE 0: store C as fp16. MODE 1: store fp32 C = acc + bias + half(peb).
#define H_TILEB 18432
#define H_STGB  (2 * H_TILEB)

template <int MODE>
__global__ void __launch_bounds__(256) hgemm_pipe(
    const __half* __restrict__ A, const __half* __restrict__ BT,
    const float* __restrict__ bias, const __half* __restrict__ peb,
    void* __restrict__ Cv, int bm0) {
    extern __shared__ char hsm[];
    const int tid = threadIdx.x;
    const int bn = (blockIdx.x & 3) << 7;
    const int bm = bm0 + (blockIdx.y << 7);

    const int lane = tid & 31;
    const int g = lane >> 2;
    const int tig = lane & 3;
    const int w = tid >> 5;
    const int wm = (w >> 2) * 64;
    const int wn = (w & 3) * 32;

    const int li = lane >> 3;
    const int wi = lane & 7;
    const int rowA = wi + ((li & 1) << 3);
    const int kolA = (li >> 1) << 3;
    const int kolB = (li & 1) << 3;

    const int crow = tid >> 1;
    const int cseg = (tid & 1) << 5;      // half offset 0 or 32

    uint32_t sbase = smaddr(hsm);

    float acc[4][4][4];
    #pragma unroll
    for (int i = 0; i < 4; i++)
        #pragma unroll
        for (int j = 0; j < 4; j++)
            #pragma unroll
            for (int e = 0; e < 4; e++) acc[i][j][e] = 0.f;

#define H_ISSUE(cc, ss)                                                         \
    do {                                                                        \
        uint32_t ab_ = sbase + (ss) * H_STGB;                                   \
        uint32_t bb_ = ab_ + H_TILEB;                                           \
        int kk_ = (cc) << 6;                                                    \
        const __half* ga_ = A + (size_t)(bm + crow) * CCH + kk_ + cseg;         \
        uint32_t da_ = ab_ + crow * 144 + cseg * 2;                             \
        cpasync16(da_, ga_);                                                    \
        cpasync16(da_ + 16, ga_ + 8);                                           \
        cpasync16(da_ + 32, ga_ + 16);                                          \
        cpasync16(da_ + 48, ga_ + 24);                                          \
        const __half* gb_ = BT + (size_t)(bn + crow) * CCH + kk_ + cseg;        \
        uint32_t db_ = bb_ + crow * 144 + cseg * 2;                             \
        cpasync16(db_, gb_);                                                    \
        cpasync16(db_ + 16, gb_ + 8);                                           \
        cpasync16(db_ + 32, gb_ + 16);                                          \
        cpasync16(db_ + 48, gb_ + 24);                                          \
        cp_commit();                                                            \
    } while (0)

    H_ISSUE(0, 0);
    H_ISSUE(1, 1);

    int stg = 0;
    for (int c = 0; c < 8; c++) {
        if (c + 1 < 8) asm volatile("cp.async.wait_group 1;");
        else           asm volatile("cp.async.wait_group 0;");
        __syncthreads();
        if (c + 2 < 8) {
            int ns = stg + 2; if (ns >= 3) ns -= 3;
            H_ISSUE(c + 2, ns);
        }
        uint32_t sA = sbase + stg * H_STGB;
        uint32_t sB = sA + H_TILEB;
        #pragma unroll
        for (int ks = 0; ks < 4; ks++) {
            int ko = ks << 4;
            uint32_t af[4][4];
            #pragma unroll
            for (int mt = 0; mt < 4; mt++) {
                uint32_t addr = sA +
                    (uint32_t)(((wm + (mt << 4) + rowA) * 72 + ko + kolA) << 1);
                ldsm_x4(addr, af[mt][0], af[mt][1], af[mt][2], af[mt][3]);
            }
            uint32_t bf[4][2];
            #pragma unroll
            for (int nt = 0; nt < 4; nt++) {
                uint32_t addr = sB +
                    (uint32_t)(((wn + (nt << 3) + wi) * 72 + ko + kolB) << 1);
                ldsm_x2(addr, bf[nt][0], bf[nt][1]);
            }
            #pragma unroll
            for (int mt = 0; mt < 4; mt++)
                #pragma unroll
                for (int nt = 0; nt < 4; nt++)
                    mma_f16(acc[mt][nt], af[mt], bf[nt]);
        }
        stg++; if (stg >= 3) stg = 0;
    }

    #pragma unroll
    for (int mt = 0; mt < 4; mt++) {
        int row = bm + wm + (mt << 4) + g;
        #pragma unroll
        for (int nt = 0; nt < 4; nt++) {
            int col = wn + (nt << 3) + (tig << 1);
            if (MODE == 0) {
                __half* C = (__half*)Cv;
                __half2 h0 = __floats2half2_rn(acc[mt][nt][0], acc[mt][nt][1]);
                __half2 h1 = __floats2half2_rn(acc[mt][nt][2], acc[mt][nt][3]);
                *reinterpret_cast<__half2*>(C + (size_t)row * CCH + bn + col) = h0;
                *reinterpret_cast<__half2*>(C + (size_t)(row + 8) * CCH + bn + col) = h1;
            } else {
                float* C = (float*)Cv;
                float b0 = bias[bn + col];
                float b1 = bias[bn + col + 1];
                float2 p0 = __half22float2(*reinterpret_cast<const __half2*>(
                    peb + (size_t)row * CCH + bn + col));
                float2 p1 = __half22float2(*reinterpret_cast<const __half2*>(
                    peb + (size_t)(row + 8) * CCH + bn + col));
                float2 v0, v1;
                v0.x = (acc[mt][nt][0] + b0) + p0.x;
                v0.y = (acc[mt][nt][1] + b1) + p0.y;
                v1.x = (acc[mt][nt][2] + b0) + p1.x;
                v1.y = (acc[mt][nt][3] + b1) + p1.y;
                *reinterpret_cast<float2*>(C + (size_t)row * CCH + bn + col) = v0;
                *reinterpret_cast<float2*>(C + (size_t)(row + 8) * CCH + bn + col) = v1;
            }
        }
    }
}

// ----------------- fp16 XtX (k-chunk 64, split-K 32) -------------------------
__global__ void __launch_bounds__(256) xtx_h(
    const __half* __restrict__ XT, float* __restrict__ part) {
    extern __shared__ char hsm[];
    const int tid = threadIdx.x;
    const int til[10] = {0, 0, 0, 0, 1, 1, 1, 2, 2, 3};
    const int tjl[10] = {0, 1, 2, 3, 1, 2, 3, 2, 3, 3};
    const int m0 = til[blockIdx.x] << 7;
    const int n0 = tjl[blockIdx.x] << 7;
    const size_t kbase = (size_t)blockIdx.y * 2048;

    const int lane = tid & 31;
    const int g = lane >> 2;
    const int tig = lane & 3;
    const int w = tid >> 5;
    const int wm = (w >> 2) * 64;
    const int wn = (w & 3) * 32;

    const int li = lane >> 3;
    const int wi = lane & 7;
    const int rowA = wi + ((li & 1) << 3);
    const int kolA = (li >> 1) << 3;
    const int kolB = (li & 1) << 3;

    const int crow = tid >> 1;
    const int cseg = (tid & 1) << 5;
    uint32_t sbase = smaddr(hsm);

    float acc[4][4][4];
    #pragma unroll
    for (int i = 0; i < 4; i++)
        #pragma unroll
        for (int j = 0; j < 4; j++)
            #pragma unroll
            for (int e = 0; e < 4; e++) acc[i][j][e] = 0.f;

#define XH_ISSUE(cc, ss)                                                        \
    do {                                                                        \
        uint32_t ab_ = sbase + (ss) * H_STGB;                                   \
        uint32_t bb_ = ab_ + H_TILEB;                                           \
        size_t kk_ = kbase + ((size_t)(cc) << 6);                               \
        const __half* ga_ = XT + (size_t)(m0 + crow) * NTOK + kk_ + cseg;       \
        uint32_t da_ = ab_ + crow * 144 + cseg * 2;                             \
        cpasync16(da_, ga_);                                                    \
        cpasync16(da_ + 16, ga_ + 8);                                           \
        cpasync16(da_ + 32, ga_ + 16);                                          \
        cpasync16(da_ + 48, ga_ + 24);                                          \
        const __half* gb_ = XT + (size_t)(n0 + crow) * NTOK + kk_ + cseg;       \
        uint32_t db_ = bb_ + crow * 144 + cseg * 2;                             \
        cpasync16(db_, gb_);                                                    \
        cpasync16(db_ + 16, gb_ + 8);                                           \
        cpasync16(db_ + 32, gb_ + 16);                                          \
        cpasync16(db_ + 48, gb_ + 24);                                          \
        cp_commit();                                                            \
    } while (0)

    XH_ISSUE(0, 0);
    XH_ISSUE(1, 1);

    int stg = 0;
    for (int c = 0; c < 32; c++) {
        if (c + 1 < 32) asm volatile("cp.async.wait_group 1;");
        else            asm volatile("cp.async.wait_group 0;");
        __syncthreads();
        if (c + 2 < 32) {
            int ns = stg + 2; if (ns >= 3) ns -= 3;
            XH_ISSUE(c + 2, ns);
        }
        uint32_t sA = sbase + stg * H_STGB;
        uint32_t sB = sA + H_TILEB;
        #pragma unroll
        for (int ks = 0; ks < 4; ks++) {
            int ko = ks << 4;
            uint32_t af[4][4];
            #pragma unroll
            for (int mt = 0; mt < 4; mt++) {
                uint32_t addr = sA +
                    (uint32_t)(((wm + (mt << 4) + rowA) * 72 + ko + kolA) << 1);
                ldsm_x4(addr, af[mt][0], af[mt][1], af[mt][2], af[mt][3]);
            }
            uint32_t bf[4][2];
            #pragma unroll
            for (int nt = 0; nt < 4; nt++) {
                uint32_t addr = sB +
                    (uint32_t)(((wn + (nt << 3) + wi) * 72 + ko + kolB) << 1);
                ldsm_x2(addr, bf[nt][0], bf[nt][1]);
            }
            #pragma unroll
            for (int mt = 0; mt < 4; mt++)
                #pragma unroll
                for (int nt = 0; nt < 4; nt++)
                    mma_f16(acc[mt][nt], af[mt], bf[nt]);
        }
        stg++; if (stg >= 3) stg = 0;
    }

    float* pp = part + (size_t)blockIdx.y * 262144;
    #pragma unroll
    for (int mt = 0; mt < 4; mt++) {
        int row = m0 + wm + (mt << 4) + g;
        #pragma unroll
        for (int nt = 0; nt < 4; nt++) {
            int col = n0 + wn + (nt << 3) + (tig << 1);
            float2 v0, v1;
            v0.x = acc[mt][nt][0]; v0.y = acc[mt][nt][1];
            v1.x = acc[mt][nt][2]; v1.y = acc[mt][nt][3];
            *reinterpret_cast<float2*>(pp + (size_t)row * 512 + col) = v0;
            *reinterpret_cast<float2*>(pp + (size_t)(row + 8) * 512 + col) = v1;
        }
    }
}

__global__ void xtx_reduce_sym(const float* __restrict__ part,
                               float* __restrict__ S) {
    int e = blockIdx.x * 1024 + threadIdx.x;
    int r = e >> 9, c = e & 511;
    int idx = ((r >> 7) <= (c >> 7)) ? e : ((c << 9) + r);
    float s = 0.f;
    #pragma unroll
    for (int ch = 0; ch < 32; ch++) s += part[(size_t)ch * 262144 + idx];
    S[e] = s;
}

// -------------- fp16 mask GEMM: K=80 (branch1) / K=32 (branch2) --------------
#define M_TILEB 6144
#define M_STGB  (3 * M_TILEB)

__global__ void __launch_bounds__(256) maskgemm_h(
    const __half* __restrict__ F, const __half* __restrict__ W1,
    const __half* __restrict__ W2, const __half* __restrict__ V,
    __half* __restrict__ vm) {
    extern __shared__ char hsm[];
    const int tid = threadIdx.x;
    const int bn = blockIdx.x << 7;
    const int bm = blockIdx.y << 7;

    const int lane = tid & 31;
    const int g = lane >> 2;
    const int tig = lane & 3;
    const int w = tid >> 5;
    const int wm = (w >> 2) * 64;
    const int wn = (w & 3) * 32;

    const int li = lane >> 3;
    const int wi = lane & 7;
    const int rowA = wi + ((li & 1) << 3);
    const int kolA = (li >> 1) << 3;
    const int kolB = (li & 1) << 3;

    const int crow = tid >> 1;
    const int ch8 = (tid & 1) << 3;
    uint32_t sbase = smaddr(hsm);

    float acc1[4][4][4], acc2[4][4][4];
    #pragma unroll
    for (int i = 0; i < 4; i++)
        #pragma unroll
        for (int j = 0; j < 4; j++)
            #pragma unroll
            for (int e = 0; e < 4; e++) { acc1[i][j][e] = 0.f; acc2[i][j][e] = 0.f; }

#define M_ISSUE(cc, ss)                                                         \
    do {                                                                        \
        uint32_t ab_ = sbase + (ss) * M_STGB;                                   \
        uint32_t b1_ = ab_ + M_TILEB;                                           \
        uint32_t b2_ = b1_ + M_TILEB;                                           \
        int kk_ = (cc) << 4;                                                    \
        uint32_t doff_ = crow * 48 + ch8 * 2;                                   \
        cpasync16(ab_ + doff_, F + (size_t)(bm + crow) * 80 + kk_ + ch8);       \
        cpasync16(b1_ + doff_, W1 + (size_t)(bn + crow) * 80 + kk_ + ch8);      \
        if ((cc) < 2)                                                           \
            cpasync16(b2_ + doff_, W2 + (size_t)(bn + crow) * 80 + kk_ + ch8);  \
        cp_commit();                                                            \
    } while (0)

    M_ISSUE(0, 0);
    M_ISSUE(1, 1);

    int stg = 0;
    for (int c = 0; c < 5; c++) {
        if (c + 1 < 5) asm volatile("cp.async.wait_group 1;");
        else           asm volatile("cp.async.wait_group 0;");
        __syncthreads();
        if (c + 2 < 5) {
            int ns = stg + 2; if (ns >= 3) ns -= 3;
            M_ISSUE(c + 2, ns);
        }
        uint32_t sA = sbase + stg * M_STGB;
        uint32_t sB1 = sA + M_TILEB;
        uint32_t sB2 = sB1 + M_TILEB;
        uint32_t af[4][4];
        #pragma unroll
        for (int mt = 0; mt < 4; mt++) {
            uint32_t addr = sA +
                (uint32_t)(((wm + (mt << 4) + rowA) * 24 + kolA) << 1);
            ldsm_x4(addr, af[mt][0], af[mt][1], af[mt][2], af[mt][3]);
        }
        #pragma unroll
        for (int nt = 0; nt < 4; nt++) {
            uint32_t roff = (uint32_t)(((wn + (nt << 3) + wi) * 24 + kolB) << 1);
            uint32_t bf1[2];
            ldsm_x2(sB1 + roff, bf1[0], bf1[1]);
            #pragma unroll
            for (int mt = 0; mt < 4; mt++)
                mma_f16(acc1[mt][nt], af[mt], bf1);
            if (c < 2) {
                uint32_t bf2[2];
                ldsm_x2(sB2 + roff, bf2[0], bf2[1]);
                #pragma unroll
                for (int mt = 0; mt < 4; mt++)
                    mma_f16(acc2[mt][nt], af[mt], bf2);
            }
        }
        stg++; if (stg >= 3) stg = 0;
    }

    #pragma unroll
    for (int mt = 0; mt < 4; mt++) {
        int row = bm + wm + (mt << 4) + g;
        #pragma unroll
        for (int nt = 0; nt < 4; nt++) {
            int col = wn + (nt << 3) + (tig << 1);
            float2 va = __half22float2(*reinterpret_cast<const __half2*>(
                V + (size_t)row * CCH + bn + col));
            float2 vb = __half22float2(*reinterpret_cast<const __half2*>(
                V + (size_t)(row + 8) * CCH + bn + col));
            float m0 = (acc1[mt][nt][0] + 1.f / (1.f + expf(-acc2[mt][nt][0]))) * va.x;
            float m1 = (acc1[mt][nt][1] + 1.f / (1.f + expf(-acc2[mt][nt][1]))) * va.y;
            float m2 = (acc1[mt][nt][2] + 1.f / (1.f + expf(-acc2[mt][nt][2]))) * vb.x;
            float m3 = (acc1[mt][nt][3] + 1.f / (1.f + expf(-acc2[mt][nt][3]))) * vb.y;
            __half2 h0 = __floats2half2_rn(m0, m1);
            __half2 h1 = __floats2half2_rn(m2, m3);
            *reinterpret_cast<__half2*>(vm + (size_t)row * CCH + bn + col) = h0;
            *reinterpret_cast<__half2*>(vm + (size_t)(row + 8) * CCH + bn + col) = h1;
        }
    }
}

// ------------------ fused conversion: x -> xh (row) + xhT (col) --------------
__global__ void xcvt_kernel(const float* __restrict__ x,
                            __half* __restrict__ xh,
                            __half* __restrict__ xhT, int y0off) {
    __shared__ float t[32][33];
    int c0 = blockIdx.x << 5;
    int t0 = (blockIdx.y + y0off) << 5;
    int tx = threadIdx.x, ty = threadIdx.y;
    #pragma unroll
    for (int r = 0; r < 32; r += 8)
        t[ty + r][tx] = x[(size_t)(t0 + ty + r) * CCH + c0 + tx];
    __syncthreads();
    #pragma unroll
    for (int r = 0; r < 32; r += 8) {
        xh[(size_t)(t0 + ty + r) * CCH + c0 + tx] = __float2half(t[ty + r][tx]);
        xhT[(size_t)(c0 + ty + r) * NTOK + t0 + tx] = __float2half(t[tx][ty + r]);
    }
}

__global__ void transpose_h_kernel(const float* __restrict__ W,
                                   __half* __restrict__ WT) {
    __shared__ float t[32][33];
    int bx = blockIdx.x << 5, by = blockIdx.y << 5;
    int tx = threadIdx.x, ty = threadIdx.y;
    #pragma unroll
    for (int r = 0; r < 32; r += 8)
        t[ty + r][tx] = W[(size_t)(by + ty + r) * CCH + bx + tx];
    __syncthreads();
    #pragma unroll
    for (int r = 0; r < 32; r += 8)
        WT[(size_t)(bx + ty + r) * CCH + by + tx] = __float2half(t[tx][ty + r]);
}

// -------------------------- legacy TF32 GEMM (small) -------------------------
#define ASF 2560
#define BSF 2176
#define STGF (ASF + BSF)

__global__ void __launch_bounds__(256) tgemm_pipe(
    const float* __restrict__ A,
    const float* __restrict__ B0, const float* __restrict__ B1,
    float* __restrict__ C0, float* __restrict__ C1, int M, int K) {
    extern __shared__ float sm[];

    const int tid = threadIdx.x;
    const int which = blockIdx.x >> 2;
    const float* B = (which == 0) ? B0 : B1;
    float* C = (which == 0) ? C0 : C1;
    const int bn = (blockIdx.x & 3) << 7;
    const int bm = blockIdx.y << 7;

    const int lane = tid & 31;
    const int g = lane >> 2;
    const int tig = lane & 3;
    const int w = tid >> 5;
    const int wm = (w >> 2) * 64;
    const int wn = (w & 3) * 32;

    const int arow = tid >> 1, acol = (tid & 1) << 3;
    const int brow = tid >> 4, bcol = (tid & 15) << 3;

    float acc[4][4][4];
    #pragma unroll
    for (int i = 0; i < 4; i++)
        #pragma unroll
        for (int j = 0; j < 4; j++)
            #pragma unroll
            for (int e = 0; e < 4; e++) acc[i][j][e] = 0.f;

    const int NK = K >> 4;

#define PIPE_ISSUE(stg, kk)                                                     \
    do {                                                                        \
        float* As_ = sm + (stg) * STGF;                                         \
        float* Bs_ = As_ + ASF;                                                 \
        const float* ga = A + (size_t)(bm + arow) * K + (kk) + acol;            \
        uint32_t sa = smaddr(As_ + arow * 20 + acol);                           \
        cpasync16(sa, ga);                                                      \
        cpasync16(sa + 16, ga + 4);                                             \
        const float* gb = B + (size_t)((kk) + brow) * CCH + bn + bcol;          \
        uint32_t sb = smaddr(Bs_ + brow * 136 + bcol);                          \
        cpasync16(sb, gb);                                                      \
        cpasync16(sb + 16, gb + 4);                                             \
        cp_commit();                                                            \
    } while (0)

    PIPE_ISSUE(0, 0);
    PIPE_ISSUE(1, 16);

    int stg = 0;
    for (int kt = 0; kt < NK; kt++) {
        if (kt + 1 < NK) asm volatile("cp.async.wait_group 1;");
        else             asm volatile("cp.async.wait_group 0;");
        __syncthreads();
        if (kt + 2 < NK) {
            int ns = stg + 2; if (ns >= 3) ns -= 3;
            PIPE_ISSUE(ns, (kt + 2) << 4);
        }
        const float* As_ = sm + stg * STGF;
        const float* Bs_ = As_ + ASF;
        #pragma unroll
        for (int ks = 0; ks < 2; ks++) {
            int kk = ks << 3;
            uint32_t af[4][4];
            #pragma unroll
            for (int mt = 0; mt < 4; mt++) {
                int m0 = wm + (mt << 4) + g;
                af[mt][0] = ld_tf32(As_ + m0 * 20 + kk + tig);
                af[mt][1] = ld_tf32(As_ + (m0 + 8) * 20 + kk + tig);
                af[mt][2] = ld_tf32(As_ + m0 * 20 + kk + tig + 4);
                af[mt][3] = ld_tf32(As_ + (m0 + 8) * 20 + kk + tig + 4);
            }
            uint32_t bf[4][2];
            #pragma unroll
            for (int nt = 0; nt < 4; nt++) {
                int n0 = wn + (nt << 3) + g;
                bf[nt][0] = ld_tf32(Bs_ + (kk + tig) * 136 + n0);
                bf[nt][1] = ld_tf32(Bs_ + (kk + tig + 4) * 136 + n0);
            }
            #pragma unroll
            for (int mt = 0; mt < 4; mt++)
                #pragma unroll
                for (int nt = 0; nt < 4; nt++)
                    mma_tf32(acc[mt][nt], af[mt], bf[nt]);
        }
        stg++; if (stg >= 3) stg = 0;
    }

    #pragma unroll
    for (int mt = 0; mt < 4; mt++) {
        int row = bm + wm + (mt << 4) + g;
        #pragma unroll
        for (int nt = 0; nt < 4; nt++) {
            int col = wn + (nt << 3) + (tig << 1);
            float2 v0, v1;
            v0.x = acc[mt][nt][0]; v0.y = acc[mt][nt][1];
            v1.x = acc[mt][nt][2]; v1.y = acc[mt][nt][3];
            *reinterpret_cast<float2*>(C + (size_t)row * CCH + bn + col) = v0;
            *reinterpret_cast<float2*>(C + (size_t)(row + 8) * CCH + bn + col) = v1;
        }
    }
}

// ---------------- per-head Gram from weights: G = Wk_h^T U_h ----------------
__global__ void __launch_bounds__(256) gramw_kernel(
    const float* __restrict__ Km, const float* __restrict__ Qm,
    float* __restrict__ gram) {
    int h = blockIdx.y;
    __shared__ float ks[64][64];
    __shared__ float qs[64][64];
    int tid = threadIdx.x;
    int lt = tid >> 2;
    int lc = (tid & 3) * 16;
    int i0 = (tid >> 4) * 4;
    int j0 = (tid & 15) * 4;
    float acc[4][4];
    #pragma unroll
    for (int i = 0; i < 4; i++)
        #pragma unroll
        for (int j = 0; j < 4; j++) acc[i][j] = 0.f;

    for (int sub = 0; sub < 8; sub++) {
        int row = sub * 64 + lt;
        const float* kp = Km + (size_t)row * CCH + h * 64 + lc;
        const float* qp = Qm + (size_t)row * CCH + h * 64 + lc;
        #pragma unroll
        for (int u = 0; u < 4; u++) {
            *reinterpret_cast<float4*>(&ks[lt][lc + u * 4]) =
                *reinterpret_cast<const float4*>(kp + u * 4);
            *reinterpret_cast<float4*>(&qs[lt][lc + u * 4]) =
                *reinterpret_cast<const float4*>(qp + u * 4);
        }
        __syncthreads();
        #pragma unroll
        for (int t = 0; t < 64; t++) {
            float4 kv = *reinterpret_cast<const float4*>(&ks[t][i0]);
            float4 qv = *reinterpret_cast<const float4*>(&qs[t][j0]);
            float kr[4] = {kv.x, kv.y, kv.z, kv.w};
            float qr[4] = {qv.x, qv.y, qv.z, qv.w};
            #pragma unroll
            for (int i = 0; i < 4; i++)
                #pragma unroll
                for (int j = 0; j < 4; j++) acc[i][j] += kr[i] * qr[j];
        }
        __syncthreads();
    }
    float* pp = gram + (size_t)h * 4096;
    #pragma unroll
    for (int i = 0; i < 4; i++)
        #pragma unroll
        for (int j = 0; j < 4; j++) pp[(i0 + i) * 64 + j0 + j] = acc[i][j];
}

__global__ void normdot_kernel(const float* __restrict__ Wk,
                               const float* __restrict__ T2,
                               const float* __restrict__ Wq,
                               const float* __restrict__ U,
                               float* __restrict__ norms) {
    int i = threadIdx.x;
    float s = 0.f;
    if (blockIdx.x == 0) {
        for (int c = 0; c < 512; c++) s += Wk[c * 512 + i] * T2[c * 512 + i];
        norms[i] = sqrtf(fmaxf(s, 0.f));
    } else {
        for (int c = 0; c < 512; c++) s += Wq[c * 512 + i] * U[c * 512 + i];
        norms[512 + i] = sqrtf(fmaxf(s, 0.f));
    }
}

// --------------------------- attention + fold into Wp -----------------------
__global__ void attn_kernel(const float* __restrict__ G,
                            const float* __restrict__ norms,
                            const float* __restrict__ rescale,
                            float* __restrict__ attn) {
    int h = blockIdx.x;
    int i = threadIdx.x;
    __shared__ float row[64][64];
    float nk = fmaxf(norms[h * 64 + i], 1e-12f);
    float rs = rescale[h];
    float mx = -1e30f;
    for (int j = 0; j < 64; j++) {
        float nq = fmaxf(norms[512 + h * 64 + j], 1e-12f);
        float vv = G[h * 4096 + i * 64 + j] * rs / (nk * nq);
        row[i][j] = vv;
        mx = fmaxf(mx, vv);
    }
    float s = 0.f;
    for (int j = 0; j < 64; j++) {
        float e = expf(row[i][j] - mx);
        row[i][j] = e;
        s += e;
    }
    float inv = 1.f / s;
    for (int j = 0; j < 64; j++)
        attn[h * 4096 + i * 64 + j] = row[i][j] * inv;
}

__global__ void wpeffT_kernel(const float* __restrict__ attn,
                              const float* __restrict__ Wp,
                              __half* __restrict__ wpeT) {
    int cp = blockIdx.x;
    int h = cp >> 6, j = cp & 63;
    int t = threadIdx.x;
    float a0 = 0.f, a1 = 0.f, a2 = 0.f, a3 = 0.f;
    const float* at = attn + h * 4096 + j;
    for (int i = 0; i < 64; i++) {
        float a = at[i * 64];
        const float* w = Wp + (size_t)((h << 6) + i) * CCH;
        a0 += a * w[t];
        a1 += a * w[t + 128];
        a2 += a * w[t + 256];
        a3 += a * w[t + 384];
    }
    wpeT[(size_t)(t) * CCH + cp]       = __float2half(a0);
    wpeT[(size_t)(t + 128) * CCH + cp] = __float2half(a1);
    wpeT[(size_t)(t + 256) * CCH + cp] = __float2half(a2);
    wpeT[(size_t)(t + 384) * CCH + cp] = __float2half(a3);
}

// --------------------- fused positional branch (dw-gelu-dw) ------------------
__global__ void __launch_bounds__(256) pe_fused_kernel(
    const __half* __restrict__ V, const float* __restrict__ w1,
    const float* __restrict__ w2, __half* __restrict__ peb) {
    __shared__ float vt[20][20][16];
    __shared__ float mid[18][18][16];
    __shared__ float w1s[16][9], w2s[16][9];

    int x0 = blockIdx.x << 4, y0 = blockIdx.y << 4, c0 = blockIdx.z << 4;
    int tid = threadIdx.x;

    if (tid < 144) {
        int cc = tid / 9, kk = tid % 9;
        w1s[cc][kk] = w1[(c0 + cc) * 9 + kk];
        w2s[cc][kk] = w2[(c0 + cc) * 9 + kk];
    }
    for (int e = tid; e < 6400; e += 256) {
        int cc = e & 15;
        int rest = e >> 4;
        int px = rest % 20, py = rest / 20;
        int xx = x0 + px - 2, yy = y0 + py - 2;
        float v = 0.f;
        if (xx >= 0 && xx < WW && yy >= 0 && yy < HH)
            v = __half2float(V[((size_t)(yy << 8) + xx) * CCH + c0 + cc]);
        vt[py][px][cc] = v;
    }
    __syncthreads();
    for (int e = tid; e < 5184; e += 256) {
        int cc = e & 15;
        int rest = e >> 4;
        int mx = rest % 18, my = rest / 18;
        int gx = x0 + mx - 1, gy = y0 + my - 1;
        bool inimg = (gx >= 0 && gx < WW && gy >= 0 && gy < HH);
        float r = 0.f;
        if (inimg) {
            float acc = 0.f;
            #pragma unroll
            for (int ky = 0; ky < 3; ky++)
                #pragma unroll
                for (int kx = 0; kx < 3; kx++)
                    acc += w1s[cc][ky * 3 + kx] * vt[my + ky][mx + kx][cc];
            r = 0.5f * acc * (1.f + erff(acc * 0.70710678118654752f));
        }
        mid[my][mx][cc] = r;
    }
    __syncthreads();
    for (int e = tid; e < 4096; e += 256) {
        int cc = e & 15;
        int ox = (e >> 4) & 15;
        int oy = e >> 8;
        float acc = 0.f;
        #pragma unroll
        for (int ky = 0; ky < 3; ky++)
            #pragma unroll
            for (int kx = 0; kx < 3; kx++)
                acc += w2s[cc][ky * 3 + kx] * mid[oy + ky][ox + kx][cc];
        size_t oi = ((size_t)((y0 + oy) << 8) + x0 + ox) * CCH + c0 + cc;
        peb[oi] = __float2half(acc);
    }
}

// --------------------------------- launch -----------------------------------
extern "C" void kernel_launch(void* const* d_in, const int* in_sizes, int n_in,
                              void* d_out, int out_size) {
    const float* x       = (const float*)d_in[0];
    const float* sar     = (const float*)d_in[1];
    const float* Wq      = (const float*)d_in[2];
    const float* Wk      = (const float*)d_in[3];
    const float* Wv      = (const float*)d_in[4];
    const float* rescale = (const float*)d_in[5];
    const float* Wp      = (const float*)d_in[6];
    const float* bp      = (const float*)d_in[7];
    const float* pe1w    = (const float*)d_in[8];
    const float* pe2w    = (const float*)d_in[9];
    const float* conv3w  = (const float*)d_in[10];
    const float* conv3b  = (const float*)d_in[11];
    const float* bng     = (const float*)d_in[12];
    const float* bnb     = (const float*)d_in[13];
    const float* sobelb  = (const float*)d_in[14];
    const float* conv2w  = (const float*)d_in[15];
    const float* conv2b  = (const float*)d_in[16];
    const float* conv32w = (const float*)d_in[17];
    const float* conv32b = (const float*)d_in[18];
    const float* dconvw  = (const float*)d_in[19];
    const float* dconvb  = (const float*)d_in[20];
    float* out = (float*)d_out;

    float *a, *ss, *bnp, *gpart, *S, *U, *T2, *gram, *norms, *attn;
    __half *vh, *xh, *xhT, *vmh, *pebh, *Fh, *W1h, *W2h, *WvTh, *wpeTh;
    cudaGetSymbolAddress((void**)&a, g_a);
    cudaGetSymbolAddress((void**)&ss, g_ss);
    cudaGetSymbolAddress((void**)&bnp, g_bnp);
    cudaGetSymbolAddress((void**)&gpart, g_gpart);
    cudaGetSymbolAddress((void**)&S, g_S);
    cudaGetSymbolAddress((void**)&U, g_U);
    cudaGetSymbolAddress((void**)&T2, g_T2);
    cudaGetSymbolAddress((void**)&gram, g_gram);
    cudaGetSymbolAddress((void**)&norms, g_norms);
    cudaGetSymbolAddress((void**)&attn, g_attn);
    cudaGetSymbolAddress((void**)&vh, g_vh);
    cudaGetSymbolAddress((void**)&xh, g_xh);
    cudaGetSymbolAddress((void**)&xhT, g_xhT);
    cudaGetSymbolAddress((void**)&vmh, g_vmh);
    cudaGetSymbolAddress((void**)&pebh, g_pebh);
    cudaGetSymbolAddress((void**)&Fh, g_Fh);
    cudaGetSymbolAddress((void**)&W1h, g_W1h);
    cudaGetSymbolAddress((void**)&W2h, g_W2h);
    cudaGetSymbolAddress((void**)&WvTh, g_WvTh);
    cudaGetSymbolAddress((void**)&wpeTh, g_wpeTh);

    const int SM_GEMM = STGF * 3 * sizeof(float);
    const int SM_H = 3 * H_STGB;                    // 110592
    const int SM_M = 3 * M_STGB;
    cudaFuncSetAttribute(tgemm_pipe,
                         cudaFuncAttributeMaxDynamicSharedMemorySize, SM_GEMM);
    cudaFuncSetAttribute(hgemm_pipe<0>,
                         cudaFuncAttributeMaxDynamicSharedMemorySize, SM_H);
    cudaFuncSetAttribute(hgemm_pipe<1>,
                         cudaFuncAttributeMaxDynamicSharedMemorySize, SM_H);
    cudaFuncSetAttribute(xtx_h,
                         cudaFuncAttributeMaxDynamicSharedMemorySize, SM_H);
    cudaFuncSetAttribute(maskgemm_h,
                         cudaFuncAttributeMaxDynamicSharedMemorySize, SM_M);

    static cudaStream_t s1 = nullptr, s2 = nullptr;
    static cudaEvent_t ev_fork = nullptr, ev_lo = nullptr, ev_cvt = nullptr,
                       ev_sar = nullptr, ev_v = nullptr, ev_aux = nullptr,
                       ev_pe = nullptr;
    if (!s1) {
        cudaStreamCreateWithFlags(&s1, cudaStreamNonBlocking);
        cudaStreamCreateWithFlags(&s2, cudaStreamNonBlocking);
        cudaEventCreateWithFlags(&ev_fork, cudaEventDisableTiming);
        cudaEventCreateWithFlags(&ev_lo, cudaEventDisableTiming);
        cudaEventCreateWithFlags(&ev_cvt, cudaEventDisableTiming);
        cudaEventCreateWithFlags(&ev_sar, cudaEventDisableTiming);
        cudaEventCreateWithFlags(&ev_v, cudaEventDisableTiming);
        cudaEventCreateWithFlags(&ev_aux, cudaEventDisableTiming);
        cudaEventCreateWithFlags(&ev_pe, cudaEventDisableTiming);
    }
    cudaStream_t s0 = 0;

    cudaEventRecord(ev_fork, s0);
    cudaStreamWaitEvent(s1, ev_fork, 0);
    cudaStreamWaitEvent(s2, ev_fork, 0);

    // ---- stream s1: x conversion in halves, then XtX/gram/attn chain ----
    xcvt_kernel<<<dim3(16, 1024), dim3(32, 8), 0, s1>>>(x, xh, xhT, 0);
    cudaEventRecord(ev_lo, s1);
    xcvt_kernel<<<dim3(16, 1024), dim3(32, 8), 0, s1>>>(x, xh, xhT, 1024);
    cudaEventRecord(ev_cvt, s1);
    xtx_h<<<dim3(10, 32), 256, SM_H, s1>>>(xhT, gpart);
    xtx_reduce_sym<<<256, 1024, 0, s1>>>(gpart, S);
    tgemm_pipe<<<dim3(8, 4), 256, SM_GEMM, s1>>>(S, Wq, Wk, U, T2, 512, CCH);
    gramw_kernel<<<dim3(1, 8), 256, 0, s1>>>(Wk, U, gram);
    normdot_kernel<<<2, 512, 0, s1>>>(Wk, T2, Wq, U, norms);
    attn_kernel<<<8, 64, 0, s1>>>(gram, norms, rescale, attn);
    wpeffT_kernel<<<512, 128, 0, s1>>>(attn, Wp, wpeTh);
    cudaEventRecord(ev_aux, s1);

    // ---- stream s2: SAR path (independent) ----
    conv3_kernel<<<256, 256, 0, s2>>>(sar, conv3w, conv3b, a);
    bnstats_kernel<<<2, 512, 0, s2>>>(a, bng, bnb, bnp);
    sobel_ss_kernel<<<256, 256, 0, s2>>>(a, bnp, sobelb, ss);
    fbuild_kernel<<<1024, 256, 0, s2>>>(ss, Fh);
    wbuild_kernel<<<1, 512, 0, s2>>>(conv2w, conv2b, conv32w, conv32b,
                                     dconvw, dconvb, W1h, W2h);
    cudaEventRecord(ev_sar, s2);

    // ---- stream 0: Wv transpose, vproj in halves, gated mask ----
    transpose_h_kernel<<<dim3(16, 16), dim3(32, 8), 0, s0>>>(Wv, WvTh);
    cudaStreamWaitEvent(s0, ev_lo, 0);
    hgemm_pipe<0><<<dim3(4, 256), 256, SM_H, s0>>>(xh, WvTh, nullptr, nullptr,
                                                   vh, 0);
    cudaStreamWaitEvent(s0, ev_cvt, 0);
    hgemm_pipe<0><<<dim3(4, 256), 256, SM_H, s0>>>(xh, WvTh, nullptr, nullptr,
                                                   vh, 32768);
    cudaEventRecord(ev_v, s0);
    cudaStreamWaitEvent(s0, ev_sar, 0);
    maskgemm_h<<<dim3(4, 512), 256, SM_M, s0>>>(Fh, W1h, W2h, vh, vmh);

    // ---- stream s2 (cont): positional branch ----
    cudaStreamWaitEvent(s2, ev_v, 0);
    pe_fused_kernel<<<dim3(16, 16, 32), 256, 0, s2>>>(vh, pe1w, pe2w, pebh);
    cudaEventRecord(ev_pe, s2);

    // ---- join: final fp16 GEMM with fused bias+pe epilogue ----
    cudaStreamWaitEvent(s0, ev_aux, 0);
    cudaStreamWaitEvent(s0, ev_pe, 0);
    hgemm_pipe<1><<<dim3(4, 512), 256, SM_H, s0>>>(vmh, wpeTh, bp, pebh, out, 0);
}

// round 13
// speedup vs baseline: 1.0568x; 1.0568x over previous
#include <cuda_runtime.h>
#include <cuda_bf16.h>
#include <cuda_fp16.h>
#include <math.h>
#include <stdint.h>

// ---------------------------------------------------------------------------
// MS_MSA — round 13: round-11 winner (k-chunk 32, 3-stage, 3 CTAs/SM) with
// xtx split-K reduced 32 -> 16 (halves partial traffic / reduce time).
// ---------------------------------------------------------------------------

#define NTOK 65536
#define CCH  512
#define HH   256
#define WW   256

// ------------------------- scratch (device globals) ------------------------
__device__ __half g_vh[33554432];
__device__ __half g_xh[33554432];
__device__ __half g_xhT[33554432];
__device__ __half g_vmh[33554432];
__device__ __half g_pebh[33554432];
__device__ __half g_Fh[5242880];
__device__ __half g_W1h[40960];
__device__ __half g_W2h[40960];
__device__ __half g_WvTh[262144];
__device__ __half g_wpeTh[262144];
__device__ float  g_a[131072];
__device__ float  g_ss[131072];
__device__ float  g_bnp[4];
__device__ float  g_gpart[4194304];   // [16][512*512]
__device__ float  g_S[262144];
__device__ float  g_U[262144];
__device__ float  g_T2[262144];
__device__ float  g_gram[32768];
__device__ float  g_norms[1024];
__device__ float  g_attn[32768];

__device__ __constant__ int c_inner[25] = {
    -1,-1,-1,-1,-1, -1,0,1,2,-1, -1,3,4,5,-1, -1,6,7,8,-1, -1,-1,-1,-1,-1};
__device__ __constant__ int c_outer[25] = {
    0,1,2,3,4, 5,-1,-1,-1,6, 7,-1,-1,-1,8, 9,-1,-1,-1,10, 11,12,13,14,15};

// ------------------------------ SAR path -----------------------------------

__global__ void conv3_kernel(const float* __restrict__ sar,
                             const float* __restrict__ w,
                             const float* __restrict__ b,
                             float* __restrict__ a) {
    int n = blockIdx.x * 256 + threadIdx.x;
    if (n >= NTOK) return;
    int y = n >> 8, x = n & 255;
    #pragma unroll
    for (int co = 0; co < 2; co++) {
        float acc = b[co];
        #pragma unroll
        for (int ci = 0; ci < 2; ci++) {
            #pragma unroll
            for (int ky = 0; ky < 3; ky++) {
                int yy = y + ky - 1;
                if (yy < 0 || yy >= HH) continue;
                #pragma unroll
                for (int kx = 0; kx < 3; kx++) {
                    int xx = x + kx - 1;
                    if (xx < 0 || xx >= WW) continue;
                    acc += w[((co * 2 + ci) * 3 + ky) * 3 + kx] *
                           sar[ci * NTOK + (yy << 8) + xx];
                }
            }
        }
        a[co * NTOK + n] = acc;
    }
}

__global__ void bnstats_kernel(const float* __restrict__ a,
                               const float* __restrict__ gg,
                               const float* __restrict__ bb,
                               float* __restrict__ bnp) {
    int c = blockIdx.x;
    __shared__ float sh[512], sh2[512];
    float s = 0.f, s2 = 0.f;
    for (int i = threadIdx.x; i < NTOK; i += 512) {
        float v = a[c * NTOK + i];
        s += v; s2 += v * v;
    }
    sh[threadIdx.x] = s; sh2[threadIdx.x] = s2;
    __syncthreads();
    for (int st = 256; st > 0; st >>= 1) {
        if (threadIdx.x < st) {
            sh[threadIdx.x] += sh[threadIdx.x + st];
            sh2[threadIdx.x] += sh2[threadIdx.x + st];
        }
        __syncthreads();
    }
    if (threadIdx.x == 0) {
        float mean = sh[0] * (1.f / NTOK);
        float var = sh2[0] * (1.f / NTOK) - mean * mean;
        float sc = gg[c] * rsqrtf(var + 1e-5f);
        bnp[c * 2] = sc;
        bnp[c * 2 + 1] = bb[c] - mean * sc;
    }
}

__global__ void sobel_ss_kernel(const float* __restrict__ a,
                                const float* __restrict__ bnp,
                                const float* __restrict__ sb,
                                float* __restrict__ ss) {
    int n = blockIdx.x * 256 + threadIdx.x;
    if (n >= NTOK) return;
    int y = n >> 8, x = n & 255;
    float sc0 = bnp[0], sh0 = bnp[1], sc1 = bnp[2], sh1 = bnp[3];
    float t[3][3];
    #pragma unroll
    for (int ky = 0; ky < 3; ky++) {
        int yy = y + ky - 1;
        #pragma unroll
        for (int kx = 0; kx < 3; kx++) {
            int xx = x + kx - 1;
            if (yy >= 0 && yy < HH && xx >= 0 && xx < WW) {
                int idx = (yy << 8) + xx;
                t[ky][kx] = a[idx] * sc0 + sh0 + a[NTOK + idx] * sc1 + sh1;
            } else t[ky][kx] = 0.f;
        }
    }
    float gy = -(t[0][0] + 2.f * t[0][1] + t[0][2]) + (t[2][0] + 2.f * t[2][1] + t[2][2]);
    float gx = -(t[0][0] + 2.f * t[1][0] + t[2][0]) + (t[0][2] + 2.f * t[1][2] + t[2][2]);
    float s0 = gy + sb[0], s1 = gx + sb[1], s2 = gy + sb[2], s3 = gx + sb[3];
    float bc0 = a[n] * sc0 + sh0;
    float bc1 = a[NTOK + n] * sc1 + sh1;
    ss[n]        = sqrtf(s0 * s0 + s1 * s1) + bc0;
    ss[NTOK + n] = sqrtf(s2 * s2 + s3 * s3) + bc1;
}

__global__ void __launch_bounds__(256) fbuild_kernel(
    const float* __restrict__ ss, __half* __restrict__ F) {
    __shared__ float Fs[64 * 80];
    int p0 = blockIdx.x * 64;
    int tid = threadIdx.x;
    int pix = tid >> 2;
    int t4 = tid & 3;
    int n = p0 + pix;
    int y = n >> 8, x = n & 255;
    for (int t = t4; t < 25; t += 4) {
        int dy = t / 5, dx = t % 5;
        int yy = y + dy - 2, xx = x + dx - 2;
        bool ok = (yy >= 0 && yy < HH && xx >= 0 && xx < WW);
        float s0 = 0.f, s1 = 0.f;
        if (ok) {
            int idx = (yy << 8) + xx;
            s0 = ss[idx];
            s1 = ss[NTOK + idx];
        }
        int ii = c_inner[t];
        int s0slot, s1slot;
        if (ii >= 0) { s0slot = ii; s1slot = 9 + ii; }
        else { int oi = c_outer[t]; s0slot = 32 + oi; s1slot = 48 + oi; }
        Fs[pix * 80 + s0slot] = s0;
        Fs[pix * 80 + s1slot] = s1;
        int vslot = (t < 13) ? (19 + t) : (64 + t - 13);
        Fs[pix * 80 + vslot] = ok ? 1.f : 0.f;
    }
    if (t4 == 0) {
        Fs[pix * 80 + 18] = 1.f;
        Fs[pix * 80 + 76] = 0.f;
        Fs[pix * 80 + 77] = 0.f;
        Fs[pix * 80 + 78] = 0.f;
        Fs[pix * 80 + 79] = 0.f;
    }
    __syncthreads();
    __half* dst = F + (size_t)p0 * 80;
    for (int e = tid; e < 64 * 80; e += 256) dst[e] = __float2half(Fs[e]);
}

__global__ void wbuild_kernel(const float* __restrict__ w2c, const float* __restrict__ b2,
                              const float* __restrict__ w32, const float* __restrict__ b32,
                              const float* __restrict__ dw, const float* __restrict__ db,
                              __half* __restrict__ W1, __half* __restrict__ W2) {
    int c = threadIdx.x;
    float w20 = w2c[c * 2], w21 = w2c[c * 2 + 1], bb2 = b2[c], bbd = db[c];
    __half* o1 = W1 + c * 80;
    __half* o2 = W2 + c * 80;
    for (int k = 0; k < 80; k++) { o1[k] = __float2half(0.f); o2[k] = __float2half(0.f); }
    for (int t = 0; t < 25; t++) {
        float d = dw[c * 25 + t];
        bool ctr = (t == 12);
        int ii = c_inner[t];
        int s0slot, s1slot;
        if (ii >= 0) { s0slot = ii; s1slot = 9 + ii; }
        else { int oi = c_outer[t]; s0slot = 32 + oi; s1slot = 48 + oi; }
        o1[s0slot] = __float2half(d * w20 + (ctr ? w20 : 0.f));
        o1[s1slot] = __float2half(d * w21 + (ctr ? w21 : 0.f));
        int vslot = (t < 13) ? (19 + t) : (64 + t - 13);
        o1[vslot] = __float2half(d * bb2 + (ctr ? bb2 : 0.f));
        if (ii >= 0) {
            o2[s0slot] = __float2half(w32[c * 18 + ii]);
            o2[s1slot] = __float2half(w32[c * 18 + 9 + ii]);
        }
    }
    o1[18] = __float2half(bbd);
    o2[18] = __float2half(b32[c]);
}

// -------------------------- MMA / async helpers ------------------------------
__device__ __forceinline__ float f2tf32(float x) {
    float r;
    asm("cvt.rna.tf32.f32 %0, %1;" : "=f"(r) : "f"(x));
    return r;
}

__device__ __forceinline__ uint32_t ld_tf32(const float* p) {
    return __float_as_uint(f2tf32(*p));
}

__device__ __forceinline__ void mma_tf32(float* c, const uint32_t* a,
                                         const uint32_t* b) {
    asm volatile(
        "mma.sync.aligned.m16n8k8.row.col.f32.tf32.tf32.f32 "
        "{%0,%1,%2,%3}, {%4,%5,%6,%7}, {%8,%9}, {%0,%1,%2,%3};"
        : "+f"(c[0]), "+f"(c[1]), "+f"(c[2]), "+f"(c[3])
        : "r"(a[0]), "r"(a[1]), "r"(a[2]), "r"(a[3]), "r"(b[0]), "r"(b[1]));
}

__device__ __forceinline__ void mma_f16(float* c, const uint32_t* a,
                                        const uint32_t* b) {
    asm volatile(
        "mma.sync.aligned.m16n8k16.row.col.f32.f16.f16.f32 "
        "{%0,%1,%2,%3}, {%4,%5,%6,%7}, {%8,%9}, {%0,%1,%2,%3};"
        : "+f"(c[0]), "+f"(c[1]), "+f"(c[2]), "+f"(c[3])
        : "r"(a[0]), "r"(a[1]), "r"(a[2]), "r"(a[3]), "r"(b[0]), "r"(b[1]));
}

__device__ __forceinline__ void ldsm_x4(uint32_t addr, uint32_t& r0, uint32_t& r1,
                                        uint32_t& r2, uint32_t& r3) {
    asm volatile("ldmatrix.sync.aligned.m8n8.x4.shared.b16 {%0,%1,%2,%3}, [%4];"
                 : "=r"(r0), "=r"(r1), "=r"(r2), "=r"(r3) : "r"(addr));
}

__device__ __forceinline__ void ldsm_x2(uint32_t addr, uint32_t& r0, uint32_t& r1) {
    asm volatile("ldmatrix.sync.aligned.m8n8.x2.shared.b16 {%0,%1}, [%2];"
                 : "=r"(r0), "=r"(r1) : "r"(addr));
}

__device__ __forceinline__ uint32_t smaddr(const void* p) {
    return (uint32_t)__cvta_generic_to_shared(p);
}

__device__ __forceinline__ void cpasync16(uint32_t s, const void* g) {
    asm volatile("cp.async.cg.shared.global [%0], [%1], 16;" :: "r"(s), "l"(g));
}

__device__ __forceinline__ void cp_commit() {
    asm volatile("cp.async.commit_group;");
}

// -------------------- fp16 GEMM: C[M,512] = A[M,512] @ BT^T ------------------
// k-chunk 32, 3 stages (round-11 winner config).
#define H_TILEB 10240
#define H_STGB  (2 * H_TILEB)

template <int MODE>
__global__ void __launch_bounds__(256) hgemm_pipe(
    const __half* __restrict__ A, const __half* __restrict__ BT,
    const float* __restrict__ bias, const __half* __restrict__ peb,
    void* __restrict__ Cv, int bm0) {
    extern __shared__ char hsm[];
    const int tid = threadIdx.x;
    const int bn = (blockIdx.x & 3) << 7;
    const int bm = bm0 + (blockIdx.y << 7);

    const int lane = tid & 31;
    const int g = lane >> 2;
    const int tig = lane & 3;
    const int w = tid >> 5;
    const int wm = (w >> 2) * 64;
    const int wn = (w & 3) * 32;

    const int li = lane >> 3;
    const int wi = lane & 7;
    const int rowA = wi + ((li & 1) << 3);
    const int kolA = (li >> 1) << 3;
    const int kolB = (li & 1) << 3;

    const int crow = tid >> 1;
    const int cseg = (tid & 1) << 4;

    uint32_t sbase = smaddr(hsm);

    float acc[4][4][4];
    #pragma unroll
    for (int i = 0; i < 4; i++)
        #pragma unroll
        for (int j = 0; j < 4; j++)
            #pragma unroll
            for (int e = 0; e < 4; e++) acc[i][j][e] = 0.f;

#define H_ISSUE(cc, ss)                                                         \
    do {                                                                        \
        uint32_t ab_ = sbase + (ss) * H_STGB;                                   \
        uint32_t bb_ = ab_ + H_TILEB;                                           \
        int kk_ = (cc) << 5;                                                    \
        const __half* ga_ = A + (size_t)(bm + crow) * CCH + kk_ + cseg;         \
        uint32_t da_ = ab_ + crow * 80 + cseg * 2;                              \
        cpasync16(da_, ga_);                                                    \
        cpasync16(da_ + 16, ga_ + 8);                                           \
        const __half* gb_ = BT + (size_t)(bn + crow) * CCH + kk_ + cseg;        \
        uint32_t db_ = bb_ + crow * 80 + cseg * 2;                              \
        cpasync16(db_, gb_);                                                    \
        cpasync16(db_ + 16, gb_ + 8);                                           \
        cp_commit();                                                            \
    } while (0)

    H_ISSUE(0, 0);
    H_ISSUE(1, 1);

    int stg = 0;
    for (int c = 0; c < 16; c++) {
        if (c + 1 < 16) asm volatile("cp.async.wait_group 1;");
        else            asm volatile("cp.async.wait_group 0;");
        __syncthreads();
        if (c + 2 < 16) {
            int ns = stg + 2; if (ns >= 3) ns -= 3;
            H_ISSUE(c + 2, ns);
        }
        uint32_t sA = sbase + stg * H_STGB;
        uint32_t sB = sA + H_TILEB;
        #pragma unroll
        for (int ks = 0; ks < 2; ks++) {
            int ko = ks << 4;
            uint32_t af[4][4];
            #pragma unroll
            for (int mt = 0; mt < 4; mt++) {
                uint32_t addr = sA +
                    (uint32_t)(((wm + (mt << 4) + rowA) * 40 + ko + kolA) << 1);
                ldsm_x4(addr, af[mt][0], af[mt][1], af[mt][2], af[mt][3]);
            }
            uint32_t bf[4][2];
            #pragma unroll
            for (int nt = 0; nt < 4; nt++) {
                uint32_t addr = sB +
                    (uint32_t)(((wn + (nt << 3) + wi) * 40 + ko + kolB) << 1);
                ldsm_x2(addr, bf[nt][0], bf[nt][1]);
            }
            #pragma unroll
            for (int mt = 0; mt < 4; mt++)
                #pragma unroll
                for (int nt = 0; nt < 4; nt++)
                    mma_f16(acc[mt][nt], af[mt], bf[nt]);
        }
        stg++; if (stg >= 3) stg = 0;
    }

    #pragma unroll
    for (int mt = 0; mt < 4; mt++) {
        int row = bm + wm + (mt << 4) + g;
        #pragma unroll
        for (int nt = 0; nt < 4; nt++) {
            int col = wn + (nt << 3) + (tig << 1);
            if (MODE == 0) {
                __half* C = (__half*)Cv;
                __half2 h0 = __floats2half2_rn(acc[mt][nt][0], acc[mt][nt][1]);
                __half2 h1 = __floats2half2_rn(acc[mt][nt][2], acc[mt][nt][3]);
                *reinterpret_cast<__half2*>(C + (size_t)row * CCH + bn + col) = h0;
                *reinterpret_cast<__half2*>(C + (size_t)(row + 8) * CCH + bn + col) = h1;
            } else {
                float* C = (float*)Cv;
                float b0 = bias[bn + col];
                float b1 = bias[bn + col + 1];
                float2 p0 = __half22float2(*reinterpret_cast<const __half2*>(
                    peb + (size_t)row * CCH + bn + col));
                float2 p1 = __half22float2(*reinterpret_cast<const __half2*>(
                    peb + (size_t)(row + 8) * CCH + bn + col));
                float2 v0, v1;
                v0.x = (acc[mt][nt][0] + b0) + p0.x;
                v0.y = (acc[mt][nt][1] + b1) + p0.y;
                v1.x = (acc[mt][nt][2] + b0) + p1.x;
                v1.y = (acc[mt][nt][3] + b1) + p1.y;
                *reinterpret_cast<float2*>(C + (size_t)row * CCH + bn + col) = v0;
                *reinterpret_cast<float2*>(C + (size_t)(row + 8) * CCH + bn + col) = v1;
            }
        }
    }
}

// ----------------- fp16 XtX (k-chunk 32, split-K 16) -------------------------
__global__ void __launch_bounds__(256) xtx_h(
    const __half* __restrict__ XT, float* __restrict__ part) {
    extern __shared__ char hsm[];
    const int tid = threadIdx.x;
    const int til[10] = {0, 0, 0, 0, 1, 1, 1, 2, 2, 3};
    const int tjl[10] = {0, 1, 2, 3, 1, 2, 3, 2, 3, 3};
    const int m0 = til[blockIdx.x] << 7;
    const int n0 = tjl[blockIdx.x] << 7;
    const size_t kbase = (size_t)blockIdx.y * 4096;

    const int lane = tid & 31;
    const int g = lane >> 2;
    const int tig = lane & 3;
    const int w = tid >> 5;
    const int wm = (w >> 2) * 64;
    const int wn = (w & 3) * 32;

    const int li = lane >> 3;
    const int wi = lane & 7;
    const int rowA = wi + ((li & 1) << 3);
    const int kolA = (li >> 1) << 3;
    const int kolB = (li & 1) << 3;

    const int crow = tid >> 1;
    const int cseg = (tid & 1) << 4;
    uint32_t sbase = smaddr(hsm);

    float acc[4][4][4];
    #pragma unroll
    for (int i = 0; i < 4; i++)
        #pragma unroll
        for (int j = 0; j < 4; j++)
            #pragma unroll
            for (int e = 0; e < 4; e++) acc[i][j][e] = 0.f;

#define XH_ISSUE(cc, ss)                                                        \
    do {                                                                        \
        uint32_t ab_ = sbase + (ss) * H_STGB;                                   \
        uint32_t bb_ = ab_ + H_TILEB;                                           \
        size_t kk_ = kbase + ((size_t)(cc) << 5);                               \
        const __half* ga_ = XT + (size_t)(m0 + crow) * NTOK + kk_ + cseg;       \
        uint32_t da_ = ab_ + crow * 80 + cseg * 2;                              \
        cpasync16(da_, ga_);                                                    \
        cpasync16(da_ + 16, ga_ + 8);                                           \
        const __half* gb_ = XT + (size_t)(n0 + crow) * NTOK + kk_ + cseg;       \
        uint32_t db_ = bb_ + crow * 80 + cseg * 2;                              \
        cpasync16(db_, gb_);                                                    \
        cpasync16(db_ + 16, gb_ + 8);                                           \
        cp_commit();                                                            \
    } while (0)

    XH_ISSUE(0, 0);
    XH_ISSUE(1, 1);

    int stg = 0;
    for (int c = 0; c < 128; c++) {
        if (c + 1 < 128) asm volatile("cp.async.wait_group 1;");
        else             asm volatile("cp.async.wait_group 0;");
        __syncthreads();
        if (c + 2 < 128) {
            int ns = stg + 2; if (ns >= 3) ns -= 3;
            XH_ISSUE(c + 2, ns);
        }
        uint32_t sA = sbase + stg * H_STGB;
        uint32_t sB = sA + H_TILEB;
        #pragma unroll
        for (int ks = 0; ks < 2; ks++) {
            int ko = ks << 4;
            uint32_t af[4][4];
            #pragma unroll
            for (int mt = 0; mt < 4; mt++) {
                uint32_t addr = sA +
                    (uint32_t)(((wm + (mt << 4) + rowA) * 40 + ko + kolA) << 1);
                ldsm_x4(addr, af[mt][0], af[mt][1], af[mt][2], af[mt][3]);
            }
            uint32_t bf[4][2];
            #pragma unroll
            for (int nt = 0; nt < 4; nt++) {
                uint32_t addr = sB +
                    (uint32_t)(((wn + (nt << 3) + wi) * 40 + ko + kolB) << 1);
                ldsm_x2(addr, bf[nt][0], bf[nt][1]);
            }
            #pragma unroll
            for (int mt = 0; mt < 4; mt++)
                #pragma unroll
                for (int nt = 0; nt < 4; nt++)
                    mma_f16(acc[mt][nt], af[mt], bf[nt]);
        }
        stg++; if (stg >= 3) stg = 0;
    }

    float* pp = part + (size_t)blockIdx.y * 262144;
    #pragma unroll
    for (int mt = 0; mt < 4; mt++) {
        int row = m0 + wm + (mt << 4) + g;
        #pragma unroll
        for (int nt = 0; nt < 4; nt++) {
            int col = n0 + wn + (nt << 3) + (tig << 1);
            float2 v0, v1;
            v0.x = acc[mt][nt][0]; v0.y = acc[mt][nt][1];
            v1.x = acc[mt][nt][2]; v1.y = acc[mt][nt][3];
            *reinterpret_cast<float2*>(pp + (size_t)row * 512 + col) = v0;
            *reinterpret_cast<float2*>(pp + (size_t)(row + 8) * 512 + col) = v1;
        }
    }
}

__global__ void xtx_reduce_sym(const float* __restrict__ part,
                               float* __restrict__ S) {
    int e = blockIdx.x * 1024 + threadIdx.x;
    int r = e >> 9, c = e & 511;
    int idx = ((r >> 7) <= (c >> 7)) ? e : ((c << 9) + r);
    float s = 0.f;
    #pragma unroll
    for (int ch = 0; ch < 16; ch++) s += part[(size_t)ch * 262144 + idx];
    S[e] = s;
}

// -------------- fp16 mask GEMM: K=80 (branch1) / K=32 (branch2) --------------
#define M_TILEB 6144
#define M_STGB  (3 * M_TILEB)

__global__ void __launch_bounds__(256) maskgemm_h(
    const __half* __restrict__ F, const __half* __restrict__ W1,
    const __half* __restrict__ W2, const __half* __restrict__ V,
    __half* __restrict__ vm) {
    extern __shared__ char hsm[];
    const int tid = threadIdx.x;
    const int bn = blockIdx.x << 7;
    const int bm = blockIdx.y << 7;

    const int lane = tid & 31;
    const int g = lane >> 2;
    const int tig = lane & 3;
    const int w = tid >> 5;
    const int wm = (w >> 2) * 64;
    const int wn = (w & 3) * 32;

    const int li = lane >> 3;
    const int wi = lane & 7;
    const int rowA = wi + ((li & 1) << 3);
    const int kolA = (li >> 1) << 3;
    const int kolB = (li & 1) << 3;

    const int crow = tid >> 1;
    const int ch8 = (tid & 1) << 3;
    uint32_t sbase = smaddr(hsm);

    float acc1[4][4][4], acc2[4][4][4];
    #pragma unroll
    for (int i = 0; i < 4; i++)
        #pragma unroll
        for (int j = 0; j < 4; j++)
            #pragma unroll
            for (int e = 0; e < 4; e++) { acc1[i][j][e] = 0.f; acc2[i][j][e] = 0.f; }

#define M_ISSUE(cc, ss)                                                         \
    do {                                                                        \
        uint32_t ab_ = sbase + (ss) * M_STGB;                                   \
        uint32_t b1_ = ab_ + M_TILEB;                                           \
        uint32_t b2_ = b1_ + M_TILEB;                                           \
        int kk_ = (cc) << 4;                                                    \
        uint32_t doff_ = crow * 48 + ch8 * 2;                                   \
        cpasync16(ab_ + doff_, F + (size_t)(bm + crow) * 80 + kk_ + ch8);       \
        cpasync16(b1_ + doff_, W1 + (size_t)(bn + crow) * 80 + kk_ + ch8);      \
        if ((cc) < 2)                                                           \
            cpasync16(b2_ + doff_, W2 + (size_t)(bn + crow) * 80 + kk_ + ch8);  \
        cp_commit();                                                            \
    } while (0)

    M_ISSUE(0, 0);
    M_ISSUE(1, 1);

    int stg = 0;
    for (int c = 0; c < 5; c++) {
        if (c + 1 < 5) asm volatile("cp.async.wait_group 1;");
        else           asm volatile("cp.async.wait_group 0;");
        __syncthreads();
        if (c + 2 < 5) {
            int ns = stg + 2; if (ns >= 3) ns -= 3;
            M_ISSUE(c + 2, ns);
        }
        uint32_t sA = sbase + stg * M_STGB;
        uint32_t sB1 = sA + M_TILEB;
        uint32_t sB2 = sB1 + M_TILEB;
        uint32_t af[4][4];
        #pragma unroll
        for (int mt = 0; mt < 4; mt++) {
            uint32_t addr = sA +
                (uint32_t)(((wm + (mt << 4) + rowA) * 24 + kolA) << 1);
            ldsm_x4(addr, af[mt][0], af[mt][1], af[mt][2], af[mt][3]);
        }
        #pragma unroll
        for (int nt = 0; nt < 4; nt++) {
            uint32_t roff = (uint32_t)(((wn + (nt << 3) + wi) * 24 + kolB) << 1);
            uint32_t bf1[2];
            ldsm_x2(sB1 + roff, bf1[0], bf1[1]);
            #pragma unroll
            for (int mt = 0; mt < 4; mt++)
                mma_f16(acc1[mt][nt], af[mt], bf1);
            if (c < 2) {
                uint32_t bf2[2];
                ldsm_x2(sB2 + roff, bf2[0], bf2[1]);
                #pragma unroll
                for (int mt = 0; mt < 4; mt++)
                    mma_f16(acc2[mt][nt], af[mt], bf2);
            }
        }
        stg++; if (stg >= 3) stg = 0;
    }

    #pragma unroll
    for (int mt = 0; mt < 4; mt++) {
        int row = bm + wm + (mt << 4) + g;
        #pragma unroll
        for (int nt = 0; nt < 4; nt++) {
            int col = wn + (nt << 3) + (tig << 1);
            float2 va = __half22float2(*reinterpret_cast<const __half2*>(
                V + (size_t)row * CCH + bn + col));
            float2 vb = __half22float2(*reinterpret_cast<const __half2*>(
                V + (size_t)(row + 8) * CCH + bn + col));
            float m0 = (acc1[mt][nt][0] + 1.f / (1.f + expf(-acc2[mt][nt][0]))) * va.x;
            float m1 = (acc1[mt][nt][1] + 1.f / (1.f + expf(-acc2[mt][nt][1]))) * va.y;
            float m2 = (acc1[mt][nt][2] + 1.f / (1.f + expf(-acc2[mt][nt][2]))) * vb.x;
            float m3 = (acc1[mt][nt][3] + 1.f / (1.f + expf(-acc2[mt][nt][3]))) * vb.y;
            __half2 h0 = __floats2half2_rn(m0, m1);
            __half2 h1 = __floats2half2_rn(m2, m3);
            *reinterpret_cast<__half2*>(vm + (size_t)row * CCH + bn + col) = h0;
            *reinterpret_cast<__half2*>(vm + (size_t)(row + 8) * CCH + bn + col) = h1;
        }
    }
}

// ------------------ fused conversion: x -> xh (row) + xhT (col) --------------
__global__ void xcvt_kernel(const float* __restrict__ x,
                            __half* __restrict__ xh,
                            __half* __restrict__ xhT, int y0off) {
    __shared__ float t[32][33];
    int c0 = blockIdx.x << 5;
    int t0 = (blockIdx.y + y0off) << 5;
    int tx = threadIdx.x, ty = threadIdx.y;
    #pragma unroll
    for (int r = 0; r < 32; r += 8)
        t[ty + r][tx] = x[(size_t)(t0 + ty + r) * CCH + c0 + tx];
    __syncthreads();
    #pragma unroll
    for (int r = 0; r < 32; r += 8) {
        xh[(size_t)(t0 + ty + r) * CCH + c0 + tx] = __float2half(t[ty + r][tx]);
        xhT[(size_t)(c0 + ty + r) * NTOK + t0 + tx] = __float2half(t[tx][ty + r]);
    }
}

__global__ void transpose_h_kernel(const float* __restrict__ W,
                                   __half* __restrict__ WT) {
    __shared__ float t[32][33];
    int bx = blockIdx.x << 5, by = blockIdx.y << 5;
    int tx = threadIdx.x, ty = threadIdx.y;
    #pragma unroll
    for (int r = 0; r < 32; r += 8)
        t[ty + r][tx] = W[(size_t)(by + ty + r) * CCH + bx + tx];
    __syncthreads();
    #pragma unroll
    for (int r = 0; r < 32; r += 8)
        WT[(size_t)(bx + ty + r) * CCH + by + tx] = __float2half(t[tx][ty + r]);
}

// -------------------------- legacy TF32 GEMM (small) -------------------------
#define ASF 2560
#define BSF 2176
#define STGF (ASF + BSF)

__global__ void __launch_bounds__(256) tgemm_pipe(
    const float* __restrict__ A,
    const float* __restrict__ B0, const float* __restrict__ B1,
    float* __restrict__ C0, float* __restrict__ C1, int M, int K) {
    extern __shared__ float sm[];

    const int tid = threadIdx.x;
    const int which = blockIdx.x >> 2;
    const float* B = (which == 0) ? B0 : B1;
    float* C = (which == 0) ? C0 : C1;
    const int bn = (blockIdx.x & 3) << 7;
    const int bm = blockIdx.y << 7;

    const int lane = tid & 31;
    const int g = lane >> 2;
    const int tig = lane & 3;
    const int w = tid >> 5;
    const int wm = (w >> 2) * 64;
    const int wn = (w & 3) * 32;

    const int arow = tid >> 1, acol = (tid & 1) << 3;
    const int brow = tid >> 4, bcol = (tid & 15) << 3;

    float acc[4][4][4];
    #pragma unroll
    for (int i = 0; i < 4; i++)
        #pragma unroll
        for (int j = 0; j < 4; j++)
            #pragma unroll
            for (int e = 0; e < 4; e++) acc[i][j][e] = 0.f;

    const int NK = K >> 4;

#define PIPE_ISSUE(stg, kk)                                                     \
    do {                                                                        \
        float* As_ = sm + (stg) * STGF;                                         \
        float* Bs_ = As_ + ASF;                                                 \
        const float* ga = A + (size_t)(bm + arow) * K + (kk) + acol;            \
        uint32_t sa = smaddr(As_ + arow * 20 + acol);                           \
        cpasync16(sa, ga);                                                      \
        cpasync16(sa + 16, ga + 4);                                             \
        const float* gb = B + (size_t)((kk) + brow) * CCH + bn + bcol;          \
        uint32_t sb = smaddr(Bs_ + brow * 136 + bcol);                          \
        cpasync16(sb, gb);                                                      \
        cpasync16(sb + 16, gb + 4);                                             \
        cp_commit();                                                            \
    } while (0)

    PIPE_ISSUE(0, 0);
    PIPE_ISSUE(1, 16);

    int stg = 0;
    for (int kt = 0; kt < NK; kt++) {
        if (kt + 1 < NK) asm volatile("cp.async.wait_group 1;");
        else             asm volatile("cp.async.wait_group 0;");
        __syncthreads();
        if (kt + 2 < NK) {
            int ns = stg + 2; if (ns >= 3) ns -= 3;
            PIPE_ISSUE(ns, (kt + 2) << 4);
        }
        const float* As_ = sm + stg * STGF;
        const float* Bs_ = As_ + ASF;
        #pragma unroll
        for (int ks = 0; ks < 2; ks++) {
            int kk = ks << 3;
            uint32_t af[4][4];
            #pragma unroll
            for (int mt = 0; mt < 4; mt++) {
                int m0 = wm + (mt << 4) + g;
                af[mt][0] = ld_tf32(As_ + m0 * 20 + kk + tig);
                af[mt][1] = ld_tf32(As_ + (m0 + 8) * 20 + kk + tig);
                af[mt][2] = ld_tf32(As_ + m0 * 20 + kk + tig + 4);
                af[mt][3] = ld_tf32(As_ + (m0 + 8) * 20 + kk + tig + 4);
            }
            uint32_t bf[4][2];
            #pragma unroll
            for (int nt = 0; nt < 4; nt++) {
                int n0 = wn + (nt << 3) + g;
                bf[nt][0] = ld_tf32(Bs_ + (kk + tig) * 136 + n0);
                bf[nt][1] = ld_tf32(Bs_ + (kk + tig + 4) * 136 + n0);
            }
            #pragma unroll
            for (int mt = 0; mt < 4; mt++)
                #pragma unroll
                for (int nt = 0; nt < 4; nt++)
                    mma_tf32(acc[mt][nt], af[mt], bf[nt]);
        }
        stg++; if (stg >= 3) stg = 0;
    }

    #pragma unroll
    for (int mt = 0; mt < 4; mt++) {
        int row = bm + wm + (mt << 4) + g;
        #pragma unroll
        for (int nt = 0; nt < 4; nt++) {
            int col = wn + (nt << 3) + (tig << 1);
            float2 v0, v1;
            v0.x = acc[mt][nt][0]; v0.y = acc[mt][nt][1];
            v1.x = acc[mt][nt][2]; v1.y = acc[mt][nt][3];
            *reinterpret_cast<float2*>(C + (size_t)row * CCH + bn + col) = v0;
            *reinterpret_cast<float2*>(C + (size_t)(row + 8) * CCH + bn + col) = v1;
        }
    }
}

// ---------------- per-head Gram from weights: G = Wk_h^T U_h ----------------
__global__ void __launch_bounds__(256) gramw_kernel(
    const float* __restrict__ Km, const float* __restrict__ Qm,
    float* __restrict__ gram) {
    int h = blockIdx.y;
    __shared__ float ks[64][64];
    __shared__ float qs[64][64];
    int tid = threadIdx.x;
    int lt = tid >> 2;
    int lc = (tid & 3) * 16;
    int i0 = (tid >> 4) * 4;
    int j0 = (tid & 15) * 4;
    float acc[4][4];
    #pragma unroll
    for (int i = 0; i < 4; i++)
        #pragma unroll
        for (int j = 0; j < 4; j++) acc[i][j] = 0.f;

    for (int sub = 0; sub < 8; sub++) {
        int row = sub * 64 + lt;
        const float* kp = Km + (size_t)row * CCH + h * 64 + lc;
        const float* qp = Qm + (size_t)row * CCH + h * 64 + lc;
        #pragma unroll
        for (int u = 0; u < 4; u++) {
            *reinterpret_cast<float4*>(&ks[lt][lc + u * 4]) =
                *reinterpret_cast<const float4*>(kp + u * 4);
            *reinterpret_cast<float4*>(&qs[lt][lc + u * 4]) =
                *reinterpret_cast<const float4*>(qp + u * 4);
        }
        __syncthreads();
        #pragma unroll
        for (int t = 0; t < 64; t++) {
            float4 kv = *reinterpret_cast<const float4*>(&ks[t][i0]);
            float4 qv = *reinterpret_cast<const float4*>(&qs[t][j0]);
            float kr[4] = {kv.x, kv.y, kv.z, kv.w};
            float qr[4] = {qv.x, qv.y, qv.z, qv.w};
            #pragma unroll
            for (int i = 0; i < 4; i++)
                #pragma unroll
                for (int j = 0; j < 4; j++) acc[i][j] += kr[i] * qr[j];
        }
        __syncthreads();
    }
    float* pp = gram + (size_t)h * 4096;
    #pragma unroll
    for (int i = 0; i < 4; i++)
        #pragma unroll
        for (int j = 0; j < 4; j++) pp[(i0 + i) * 64 + j0 + j] = acc[i][j];
}

__global__ void normdot_kernel(const float* __restrict__ Wk,
                               const float* __restrict__ T2,
                               const float* __restrict__ Wq,
                               const float* __restrict__ U,
                               float* __restrict__ norms) {
    int i = threadIdx.x;
    float s = 0.f;
    if (blockIdx.x == 0) {
        for (int c = 0; c < 512; c++) s += Wk[c * 512 + i] * T2[c * 512 + i];
        norms[i] = sqrtf(fmaxf(s, 0.f));
    } else {
        for (int c = 0; c < 512; c++) s += Wq[c * 512 + i] * U[c * 512 + i];
        norms[512 + i] = sqrtf(fmaxf(s, 0.f));
    }
}

// --------------------------- attention + fold into Wp -----------------------
__global__ void attn_kernel(const float* __restrict__ G,
                            const float* __restrict__ norms,
                            const float* __restrict__ rescale,
                            float* __restrict__ attn) {
    int h = blockIdx.x;
    int i = threadIdx.x;
    __shared__ float row[64][64];
    float nk = fmaxf(norms[h * 64 + i], 1e-12f);
    float rs = rescale[h];
    float mx = -1e30f;
    for (int j = 0; j < 64; j++) {
        float nq = fmaxf(norms[512 + h * 64 + j], 1e-12f);
        float vv = G[h * 4096 + i * 64 + j] * rs / (nk * nq);
        row[i][j] = vv;
        mx = fmaxf(mx, vv);
    }
    float s = 0.f;
    for (int j = 0; j < 64; j++) {
        float e = expf(row[i][j] - mx);
        row[i][j] = e;
        s += e;
    }
    float inv = 1.f / s;
    for (int j = 0; j < 64; j++)
        attn[h * 4096 + i * 64 + j] = row[i][j] * inv;
}

__global__ void wpeffT_kernel(const float* __restrict__ attn,
                              const float* __restrict__ Wp,
                              __half* __restrict__ wpeT) {
    int cp = blockIdx.x;
    int h = cp >> 6, j = cp & 63;
    int t = threadIdx.x;
    float a0 = 0.f, a1 = 0.f, a2 = 0.f, a3 = 0.f;
    const float* at = attn + h * 4096 + j;
    for (int i = 0; i < 64; i++) {
        float a = at[i * 64];
        const float* w = Wp + (size_t)((h << 6) + i) * CCH;
        a0 += a * w[t];
        a1 += a * w[t + 128];
        a2 += a * w[t + 256];
        a3 += a * w[t + 384];
    }
    wpeT[(size_t)(t) * CCH + cp]       = __float2half(a0);
    wpeT[(size_t)(t + 128) * CCH + cp] = __float2half(a1);
    wpeT[(size_t)(t + 256) * CCH + cp] = __float2half(a2);
    wpeT[(size_t)(t + 384) * CCH + cp] = __float2half(a3);
}

// --------------------- fused positional branch (dw-gelu-dw) ------------------
__global__ void __launch_bounds__(256) pe_fused_kernel(
    const __half* __restrict__ V, const float* __restrict__ w1,
    const float* __restrict__ w2, __half* __restrict__ peb) {
    __shared__ float vt[20][20][16];
    __shared__ float mid[18][18][16];
    __shared__ float w1s[16][9], w2s[16][9];

    int x0 = blockIdx.x << 4, y0 = blockIdx.y << 4, c0 = blockIdx.z << 4;
    int tid = threadIdx.x;

    if (tid < 144) {
        int cc = tid / 9, kk = tid % 9;
        w1s[cc][kk] = w1[(c0 + cc) * 9 + kk];
        w2s[cc][kk] = w2[(c0 + cc) * 9 + kk];
    }
    for (int e = tid; e < 6400; e += 256) {
        int cc = e & 15;
        int rest = e >> 4;
        int px = rest % 20, py = rest / 20;
        int xx = x0 + px - 2, yy = y0 + py - 2;
        float v = 0.f;
        if (xx >= 0 && xx < WW && yy >= 0 && yy < HH)
            v = __half2float(V[((size_t)(yy << 8) + xx) * CCH + c0 + cc]);
        vt[py][px][cc] = v;
    }
    __syncthreads();
    for (int e = tid; e < 5184; e += 256) {
        int cc = e & 15;
        int rest = e >> 4;
        int mx = rest % 18, my = rest / 18;
        int gx = x0 + mx - 1, gy = y0 + my - 1;
        bool inimg = (gx >= 0 && gx < WW && gy >= 0 && gy < HH);
        float r = 0.f;
        if (inimg) {
            float acc = 0.f;
            #pragma unroll
            for (int ky = 0; ky < 3; ky++)
                #pragma unroll
                for (int kx = 0; kx < 3; kx++)
                    acc += w1s[cc][ky * 3 + kx] * vt[my + ky][mx + kx][cc];
            r = 0.5f * acc * (1.f + erff(acc * 0.70710678118654752f));
        }
        mid[my][mx][cc] = r;
    }
    __syncthreads();
    for (int e = tid; e < 4096; e += 256) {
        int cc = e & 15;
        int ox = (e >> 4) & 15;
        int oy = e >> 8;
        float acc = 0.f;
        #pragma unroll
        for (int ky = 0; ky < 3; ky++)
            #pragma unroll
            for (int kx = 0; kx < 3; kx++)
                acc += w2s[cc][ky * 3 + kx] * mid[oy + ky][ox + kx][cc];
        size_t oi = ((size_t)((y0 + oy) << 8) + x0 + ox) * CCH + c0 + cc;
        peb[oi] = __float2half(acc);
    }
}

// --------------------------------- launch -----------------------------------
extern "C" void kernel_launch(void* const* d_in, const int* in_sizes, int n_in,
                              void* d_out, int out_size) {
    const float* x       = (const float*)d_in[0];
    const float* sar     = (const float*)d_in[1];
    const float* Wq      = (const float*)d_in[2];
    const float* Wk      = (const float*)d_in[3];
    const float* Wv      = (const float*)d_in[4];
    const float* rescale = (const float*)d_in[5];
    const float* Wp      = (const float*)d_in[6];
    const float* bp      = (const float*)d_in[7];
    const float* pe1w    = (const float*)d_in[8];
    const float* pe2w    = (const float*)d_in[9];
    const float* conv3w  = (const float*)d_in[10];
    const float* conv3b  = (const float*)d_in[11];
    const float* bng     = (const float*)d_in[12];
    const float* bnb     = (const float*)d_in[13];
    const float* sobelb  = (const float*)d_in[14];
    const float* conv2w  = (const float*)d_in[15];
    const float* conv2b  = (const float*)d_in[16];
    const float* conv32w = (const float*)d_in[17];
    const float* conv32b = (const float*)d_in[18];
    const float* dconvw  = (const float*)d_in[19];
    const float* dconvb  = (const float*)d_in[20];
    float* out = (float*)d_out;

    float *a, *ss, *bnp, *gpart, *S, *U, *T2, *gram, *norms, *attn;
    __half *vh, *xh, *xhT, *vmh, *pebh, *Fh, *W1h, *W2h, *WvTh, *wpeTh;
    cudaGetSymbolAddress((void**)&a, g_a);
    cudaGetSymbolAddress((void**)&ss, g_ss);
    cudaGetSymbolAddress((void**)&bnp, g_bnp);
    cudaGetSymbolAddress((void**)&gpart, g_gpart);
    cudaGetSymbolAddress((void**)&S, g_S);
    cudaGetSymbolAddress((void**)&U, g_U);
    cudaGetSymbolAddress((void**)&T2, g_T2);
    cudaGetSymbolAddress((void**)&gram, g_gram);
    cudaGetSymbolAddress((void**)&norms, g_norms);
    cudaGetSymbolAddress((void**)&attn, g_attn);
    cudaGetSymbolAddress((void**)&vh, g_vh);
    cudaGetSymbolAddress((void**)&xh, g_xh);
    cudaGetSymbolAddress((void**)&xhT, g_xhT);
    cudaGetSymbolAddress((void**)&vmh, g_vmh);
    cudaGetSymbolAddress((void**)&pebh, g_pebh);
    cudaGetSymbolAddress((void**)&Fh, g_Fh);
    cudaGetSymbolAddress((void**)&W1h, g_W1h);
    cudaGetSymbolAddress((void**)&W2h, g_W2h);
    cudaGetSymbolAddress((void**)&WvTh, g_WvTh);
    cudaGetSymbolAddress((void**)&wpeTh, g_wpeTh);

    const int SM_GEMM = STGF * 3 * sizeof(float);
    const int SM_H = 3 * H_STGB;
    const int SM_M = 3 * M_STGB;
    cudaFuncSetAttribute(tgemm_pipe,
                         cudaFuncAttributeMaxDynamicSharedMemorySize, SM_GEMM);
    cudaFuncSetAttribute(hgemm_pipe<0>,
                         cudaFuncAttributeMaxDynamicSharedMemorySize, SM_H);
    cudaFuncSetAttribute(hgemm_pipe<1>,
                         cudaFuncAttributeMaxDynamicSharedMemorySize, SM_H);
    cudaFuncSetAttribute(xtx_h,
                         cudaFuncAttributeMaxDynamicSharedMemorySize, SM_H);
    cudaFuncSetAttribute(maskgemm_h,
                         cudaFuncAttributeMaxDynamicSharedMemorySize, SM_M);

    static cudaStream_t s1 = nullptr, s2 = nullptr;
    static cudaEvent_t ev_fork = nullptr, ev_lo = nullptr, ev_cvt = nullptr,
                       ev_sar = nullptr, ev_v = nullptr, ev_aux = nullptr,
                       ev_pe = nullptr;
    if (!s1) {
        cudaStreamCreateWithFlags(&s1, cudaStreamNonBlocking);
        cudaStreamCreateWithFlags(&s2, cudaStreamNonBlocking);
        cudaEventCreateWithFlags(&ev_fork, cudaEventDisableTiming);
        cudaEventCreateWithFlags(&ev_lo, cudaEventDisableTiming);
        cudaEventCreateWithFlags(&ev_cvt, cudaEventDisableTiming);
        cudaEventCreateWithFlags(&ev_sar, cudaEventDisableTiming);
        cudaEventCreateWithFlags(&ev_v, cudaEventDisableTiming);
        cudaEventCreateWithFlags(&ev_aux, cudaEventDisableTiming);
        cudaEventCreateWithFlags(&ev_pe, cudaEventDisableTiming);
    }
    cudaStream_t s0 = 0;

    cudaEventRecord(ev_fork, s0);
    cudaStreamWaitEvent(s1, ev_fork, 0);
    cudaStreamWaitEvent(s2, ev_fork, 0);

    // ---- stream s1: x conversion in halves, then XtX/gram/attn chain ----
    xcvt_kernel<<<dim3(16, 1024), dim3(32, 8), 0, s1>>>(x, xh, xhT, 0);
    cudaEventRecord(ev_lo, s1);
    xcvt_kernel<<<dim3(16, 1024), dim3(32, 8), 0, s1>>>(x, xh, xhT, 1024);
    cudaEventRecord(ev_cvt, s1);
    xtx_h<<<dim3(10, 16), 256, SM_H, s1>>>(xhT, gpart);
    xtx_reduce_sym<<<256, 1024, 0, s1>>>(gpart, S);
    tgemm_pipe<<<dim3(8, 4), 256, SM_GEMM, s1>>>(S, Wq, Wk, U, T2, 512, CCH);
    gramw_kernel<<<dim3(1, 8), 256, 0, s1>>>(Wk, U, gram);
    normdot_kernel<<<2, 512, 0, s1>>>(Wk, T2, Wq, U, norms);
    attn_kernel<<<8, 64, 0, s1>>>(gram, norms, rescale, attn);
    wpeffT_kernel<<<512, 128, 0, s1>>>(attn, Wp, wpeTh);
    cudaEventRecord(ev_aux, s1);

    // ---- stream s2: SAR path (independent) ----
    conv3_kernel<<<256, 256, 0, s2>>>(sar, conv3w, conv3b, a);
    bnstats_kernel<<<2, 512, 0, s2>>>(a, bng, bnb, bnp);
    sobel_ss_kernel<<<256, 256, 0, s2>>>(a, bnp, sobelb, ss);
    fbuild_kernel<<<1024, 256, 0, s2>>>(ss, Fh);
    wbuild_kernel<<<1, 512, 0, s2>>>(conv2w, conv2b, conv32w, conv32b,
                                     dconvw, dconvb, W1h, W2h);
    cudaEventRecord(ev_sar, s2);

    // ---- stream 0: Wv transpose, vproj in halves, gated mask ----
    transpose_h_kernel<<<dim3(16, 16), dim3(32, 8), 0, s0>>>(Wv, WvTh);
    cudaStreamWaitEvent(s0, ev_lo, 0);
    hgemm_pipe<0><<<dim3(4, 256), 256, SM_H, s0>>>(xh, WvTh, nullptr, nullptr,
                                                   vh, 0);
    cudaStreamWaitEvent(s0, ev_cvt, 0);
    hgemm_pipe<0><<<dim3(4, 256), 256, SM_H, s0>>>(xh, WvTh, nullptr, nullptr,
                                                   vh, 32768);
    cudaEventRecord(ev_v, s0);
    cudaStreamWaitEvent(s0, ev_sar, 0);
    maskgemm_h<<<dim3(4, 512), 256, SM_M, s0>>>(Fh, W1h, W2h, vh, vmh);

    // ---- stream s2 (cont): positional branch ----
    cudaStreamWaitEvent(s2, ev_v, 0);
    pe_fused_kernel<<<dim3(16, 16, 32), 256, 0, s2>>>(vh, pe1w, pe2w, pebh);
    cudaEventRecord(ev_pe, s2);

    // ---- join: final fp16 GEMM with fused bias+pe epilogue ----
    cudaStreamWaitEvent(s0, ev_aux, 0);
    cudaStreamWaitEvent(s0, ev_pe, 0);
    hgemm_pipe<1><<<dim3(4, 512), 256, SM_H, s0>>>(vmh, wpeTh, bp, pebh, out, 0);
}